// round 3
// baseline (speedup 1.0000x reference)
#include <cuda_runtime.h>
#include <cstdint>

// Problem: LIF spiking layer, monitor='mem'
//   inputs: [B=64, T=1024, IN=256] f32   (d_in[0], 16777216 elems)
//   w:      [IN=256, OUT=256] f32        (d_in[1], 65536 elems)
//   out U:  [B=64, T=1024, OUT=256] f32  (d_out,   16777216 elems)
//
// Stage 1: x = inputs @ w  written directly into d_out (scratch-free).
// Stage 2: in-place sequential LIF scan per (b, out) lane, x -> U.

// ---------------------------------------------------------------------------
// Stage 1: fp32 SGEMM  C[M,N] = A[M,K] * B[K,N],  M=65536, N=256, K=256
// 128x128 block tile, BK=8, 8x8 per thread, 256 threads/block.
// ---------------------------------------------------------------------------
namespace cfg {
constexpr int BM = 128, BN = 128, BK = 8, TM = 8, TN = 8;
}

__global__ __launch_bounds__(256) void sgemm_kernel(
    const float* __restrict__ A, const float* __restrict__ B,
    float* __restrict__ C, int M, int N, int K)
{
    using namespace cfg;
    const int cRow = blockIdx.y;
    const int cCol = blockIdx.x;

    __shared__ float As[BK * BM];  // transposed A tile: As[k][m]
    __shared__ float Bs[BK * BN];  // Bs[k][n]

    A += (size_t)cRow * BM * K;
    B += (size_t)cCol * BN;
    C += (size_t)cRow * BM * N + cCol * BN;

    const int tid = threadIdx.x;
    const int threadCol = tid % (BN / TN);  // 0..15
    const int threadRow = tid / (BN / TN);  // 0..15

    // A tile load mapping: 128 rows x 8 cols = 1024 f32 = 256 x float4
    const int innerRowA = tid / (BK / 4);   // tid/2 -> 0..127
    const int innerColA = tid % (BK / 4);   // 0..1
    // B tile load mapping: 8 rows x 128 cols
    const int innerRowB = tid / (BN / 4);   // tid/32 -> 0..7
    const int innerColB = tid % (BN / 4);   // 0..31

    float acc[TM * TN] = {0.0f};
    float regM[TM], regN[TN];

    for (int bk = 0; bk < K; bk += BK) {
        // load + transpose A tile into smem
        float4 ta = *reinterpret_cast<const float4*>(&A[(size_t)innerRowA * K + innerColA * 4]);
        As[(innerColA * 4 + 0) * BM + innerRowA] = ta.x;
        As[(innerColA * 4 + 1) * BM + innerRowA] = ta.y;
        As[(innerColA * 4 + 2) * BM + innerRowA] = ta.z;
        As[(innerColA * 4 + 3) * BM + innerRowA] = ta.w;
        // load B tile
        *reinterpret_cast<float4*>(&Bs[innerRowB * BN + innerColB * 4]) =
            *reinterpret_cast<const float4*>(&B[(size_t)innerRowB * N + innerColB * 4]);
        __syncthreads();

        A += BK;
        B += (size_t)BK * N;

#pragma unroll
        for (int dot = 0; dot < BK; ++dot) {
#pragma unroll
            for (int i = 0; i < TM; ++i) regM[i] = As[dot * BM + threadRow * TM + i];
#pragma unroll
            for (int i = 0; i < TN; ++i) regN[i] = Bs[dot * BN + threadCol * TN + i];
#pragma unroll
            for (int m = 0; m < TM; ++m)
#pragma unroll
                for (int n = 0; n < TN; ++n)
                    acc[m * TN + n] = fmaf(regM[m], regN[n], acc[m * TN + n]);
        }
        __syncthreads();
    }

#pragma unroll
    for (int m = 0; m < TM; ++m) {
#pragma unroll
        for (int n = 0; n < TN; n += 4) {
            float4 t;
            t.x = acc[m * TN + n + 0];
            t.y = acc[m * TN + n + 1];
            t.z = acc[m * TN + n + 2];
            t.w = acc[m * TN + n + 3];
            *reinterpret_cast<float4*>(
                &C[(size_t)(threadRow * TM + m) * N + threadCol * TN + n]) = t;
        }
    }
}

// ---------------------------------------------------------------------------
// Stage 2: in-place LIF scan.  X holds x = inputs@w, overwritten with U.
//   lane = (b, o); state (syn, mem) starts at 0.
//   for t in 0..T-2:
//     new_syn = dcy_syn*syn + x[t]
//     new_mem = dcy_mem*mem + scl_mem*syn      (old syn)
//     if (mem > 1) new_mem = 0                 (spike from OLD mem, reset)
//     U[t+1] = new_mem
//   U[0] = 0
// Double-buffered 16-deep register prefetch: reads of chunk c+1 are issued
// before the writes of chunk c (same thread, program order), so the in-place
// overwrite at the chunk boundary is safe.
// ---------------------------------------------------------------------------
constexpr int T_STEPS = 1024;
constexpr int OUT_C   = 256;
constexpr int CHUNK   = 16;

__global__ __launch_bounds__(128) void lif_scan_kernel(float* __restrict__ X)
{
    const int lane = blockIdx.x * blockDim.x + threadIdx.x;  // 0..16383
    const int b = lane >> 8;
    const int o = lane & 255;
    float* base = X + (size_t)b * T_STEPS * OUT_C + o;

    // decay constants, fp32 (match jnp float32 exp)
    const float dcy_syn = 0.81873075307798185867f;   // exp(-0.2)
    const float dcy_mem = 0.90483741803595957316f;   // exp(-0.1)
    const float scl_mem = 1.0f - dcy_mem;

    float syn = 0.0f, mem = 0.0f;

    float buf[2][CHUNK];

    // prefetch chunk 0 (t = 0..15)
#pragma unroll
    for (int i = 0; i < CHUNK; ++i)
        buf[0][i] = base[(size_t)i * OUT_C];

    // U[0] = 0 (x[0] already in register)
    base[0] = 0.0f;

    int cur = 0;
    constexpr int NCHUNK = T_STEPS / CHUNK;  // 64
    for (int c = 0; c < NCHUNK; ++c) {
        // prefetch next chunk before writing into its region
        if (c + 1 < NCHUNK) {
#pragma unroll
            for (int i = 0; i < CHUNK; ++i)
                buf[cur ^ 1][i] = base[(size_t)((c + 1) * CHUNK + i) * OUT_C];
        }
#pragma unroll
        for (int i = 0; i < CHUNK; ++i) {
            const int t = c * CHUNK + i;
            if (t < T_STEPS - 1) {          // steps t = 0..1022
                const float x = buf[cur][i];
                const float nsyn = fmaf(dcy_syn, syn, x);
                float nmem = fmaf(dcy_mem, mem, scl_mem * syn);
                if (mem > 1.0f) nmem = 0.0f;   // spike on OLD mem -> reset
                base[(size_t)(t + 1) * OUT_C] = nmem;
                syn = nsyn;
                mem = nmem;
            }
        }
        cur ^= 1;
    }
}

// ---------------------------------------------------------------------------
extern "C" void kernel_launch(void* const* d_in, const int* in_sizes, int n_in,
                              void* d_out, int out_size)
{
    const float* inputs = (const float*)d_in[0];  // [64,1024,256]
    const float* w      = (const float*)d_in[1];  // [256,256]
    float* out          = (float*)d_out;          // [64,1024,256]

    const int M = 64 * 1024;   // 65536
    const int N = 256;
    const int K = 256;

    // Stage 1: x = inputs @ w  -> d_out
    dim3 gemmGrid(N / cfg::BN, M / cfg::BM);   // (2, 512)
    sgemm_kernel<<<gemmGrid, 256>>>(inputs, w, out, M, N, K);

    // Stage 2: in-place scan x -> U
    const int lanes = 64 * OUT_C;              // 16384
    lif_scan_kernel<<<lanes / 128, 128>>>(out);
}

// round 6
// speedup vs baseline: 1.4854x; 1.4854x over previous
#include <cuda_runtime.h>
#include <cstdint>

// Problem: LIF spiking layer, monitor='mem'
//   inputs: [B=64, T=1024, IN=256] f32   (d_in[0])
//   w:      [IN=256, OUT=256] f32        (d_in[1])
//   out U:  [B=64, T=1024, OUT=256] f32  (d_out)
//
// Stage 1: x = inputs @ w  written directly into d_out (scratch-free).
// Stage 2: in-place sequential LIF scan per (b, out) lane, x -> U,
//          cp.async smem-staged double-buffer pipeline.

// ---------------------------------------------------------------------------
// Stage 1: fp32 SGEMM  C[M,N] = A[M,K] * B[K,N],  M=65536, N=256, K=256
// (measured at ~95% of fp32 FFMA roofline — unchanged)
// ---------------------------------------------------------------------------
namespace cfg {
constexpr int BM = 128, BN = 128, BK = 8, TM = 8, TN = 8;
}

__global__ __launch_bounds__(256) void sgemm_kernel(
    const float* __restrict__ A, const float* __restrict__ B,
    float* __restrict__ C, int M, int N, int K)
{
    using namespace cfg;
    const int cRow = blockIdx.y;
    const int cCol = blockIdx.x;

    __shared__ float As[BK * BM];  // transposed A tile: As[k][m]
    __shared__ float Bs[BK * BN];  // Bs[k][n]

    A += (size_t)cRow * BM * K;
    B += (size_t)cCol * BN;
    C += (size_t)cRow * BM * N + cCol * BN;

    const int tid = threadIdx.x;
    const int threadCol = tid % (BN / TN);  // 0..15
    const int threadRow = tid / (BN / TN);  // 0..15

    const int innerRowA = tid / (BK / 4);   // 0..127
    const int innerColA = tid % (BK / 4);   // 0..1
    const int innerRowB = tid / (BN / 4);   // 0..7
    const int innerColB = tid % (BN / 4);   // 0..31

    float acc[TM * TN] = {0.0f};
    float regM[TM], regN[TN];

    for (int bk = 0; bk < K; bk += BK) {
        float4 ta = *reinterpret_cast<const float4*>(&A[(size_t)innerRowA * K + innerColA * 4]);
        As[(innerColA * 4 + 0) * BM + innerRowA] = ta.x;
        As[(innerColA * 4 + 1) * BM + innerRowA] = ta.y;
        As[(innerColA * 4 + 2) * BM + innerRowA] = ta.z;
        As[(innerColA * 4 + 3) * BM + innerRowA] = ta.w;
        *reinterpret_cast<float4*>(&Bs[innerRowB * BN + innerColB * 4]) =
            *reinterpret_cast<const float4*>(&B[(size_t)innerRowB * N + innerColB * 4]);
        __syncthreads();

        A += BK;
        B += (size_t)BK * N;

#pragma unroll
        for (int dot = 0; dot < BK; ++dot) {
#pragma unroll
            for (int i = 0; i < TM; ++i) regM[i] = As[dot * BM + threadRow * TM + i];
#pragma unroll
            for (int i = 0; i < TN; ++i) regN[i] = Bs[dot * BN + threadCol * TN + i];
#pragma unroll
            for (int m = 0; m < TM; ++m)
#pragma unroll
                for (int n = 0; n < TN; ++n)
                    acc[m * TN + n] = fmaf(regM[m], regN[n], acc[m * TN + n]);
        }
        __syncthreads();
    }

#pragma unroll
    for (int m = 0; m < TM; ++m) {
#pragma unroll
        for (int n = 0; n < TN; n += 4) {
            float4 t;
            t.x = acc[m * TN + n + 0];
            t.y = acc[m * TN + n + 1];
            t.z = acc[m * TN + n + 2];
            t.w = acc[m * TN + n + 3];
            *reinterpret_cast<float4*>(
                &C[(size_t)(threadRow * TM + m) * N + threadCol * TN + n]) = t;
        }
    }
}

// ---------------------------------------------------------------------------
// Stage 2: in-place LIF scan with cp.async smem staging.
//
// Block = (batch b, o-half h): 128 lanes, 128 threads (thread = 1 lane).
// Tile = TS=32 timesteps x 128 lanes = 16 KB, PIPE=2 smem stages.
//
// Group accounting: tile j's cp.async group is committed at end of iter j-2
// (tiles 0,1 primed before the loop). At iter c, committed = min(c+2, NTILES).
// Tile c resident requires pending <= committed-(c+1):
//   c <= NTILES-2 -> wait_group 1;  c == NTILES-1 -> wait_group 0.
//
// In-place safety: tile c's U writes touch rows c*TS .. (c+1)*TS-1 only;
// tile c+2's load (rows (c+2)*TS..) is issued before those writes but its
// rows are first written only at iteration c+2, after that load completed.
// ---------------------------------------------------------------------------
constexpr int T_STEPS = 1024;
constexpr int OUT_C   = 256;
constexpr int TS      = 32;                 // timesteps per tile
constexpr int LPB     = 128;                // lanes per block
constexpr int NTILES  = T_STEPS / TS;       // 32
constexpr int PIPE    = 2;

__device__ __forceinline__ void cp_async16(uint32_t smem_addr, const void* gptr) {
    asm volatile("cp.async.cg.shared.global [%0], [%1], 16;"
                 :: "r"(smem_addr), "l"(gptr) : "memory");
}
__device__ __forceinline__ void cp_async_commit() {
    asm volatile("cp.async.commit_group;" ::: "memory");
}
template <int N>
__device__ __forceinline__ void cp_async_wait() {
    asm volatile("cp.async.wait_group %0;" :: "n"(N) : "memory");
}

__global__ __launch_bounds__(LPB) void lif_scan_kernel(float* __restrict__ X)
{
    __shared__ float tile[PIPE][TS * LPB];   // 2 x 16KB

    const int tid  = threadIdx.x;
    const int b    = blockIdx.x >> 1;        // batch
    const int half = blockIdx.x & 1;         // which 128-lane half
    float* base  = X + (size_t)b * T_STEPS * OUT_C + half * LPB;  // block base
    float* gbase = base + tid;                                    // THIS lane

    uint32_t smem_base;
    asm("{ .reg .u64 t; cvta.to.shared.u64 t, %1; cvt.u32.u64 %0, t; }"
        : "=r"(smem_base) : "l"(&tile[0][0]));

    // per tile: 32 rows x 32 x 16B chunks = 1024 chunks, 128 threads x 8
    auto issue_tile = [&](int c, int stage) {
#pragma unroll
        for (int k = 0; k < 8; ++k) {
            int chunk = tid + k * LPB;
            int row   = chunk >> 5;          // 0..31
            int c16   = chunk & 31;          // 0..31
            const void* g = (const char*)base +
                (size_t)(c * TS + row) * OUT_C * 4 + c16 * 16;
            uint32_t s = smem_base + stage * (TS * LPB * 4) + row * (LPB * 4) + c16 * 16;
            cp_async16(s, g);
        }
        cp_async_commit();
    };

    // prime the pipeline
    issue_tile(0, 0);
    issue_tile(1, 1);

    const float dcy_syn = 0.81873075307798185867f;   // exp(-0.2)
    const float dcy_mem = 0.90483741803595957316f;   // exp(-0.1)
    const float scl_mem = 1.0f - dcy_mem;

    float syn = 0.0f, mem = 0.0f;
    float carry = 0.0f;                       // U[0] = 0

    for (int c = 0; c < NTILES; ++c) {
        const int stage = c & (PIPE - 1);
        if (c == NTILES - 1)
            cp_async_wait<0>();               // last tile: its group is the only one
        else
            cp_async_wait<PIPE - 1>();        // tile c resident
        __syncthreads();

        // write carried value into row t0 = c*TS (x row already staged)
        gbase[(size_t)(c * TS) * OUT_C] = carry;

        const float* sm = &tile[stage][tid];
#pragma unroll
        for (int i = 0; i < TS; ++i) {
            const int t = c * TS + i;
            if (t < T_STEPS - 1) {            // t = 0..1022
                const float x    = sm[i * LPB];
                const float nsyn = fmaf(dcy_syn, syn, x);
                float nmem = fmaf(dcy_mem, mem, scl_mem * syn);
                if (mem > 1.0f) nmem = 0.0f;  // spike from OLD mem -> reset
                if (i < TS - 1)
                    gbase[(size_t)(t + 1) * OUT_C] = nmem;
                else
                    carry = nmem;             // row lands in next tile
                syn = nsyn;
                mem = nmem;
            }
        }

        __syncthreads();                      // all lanes done with stage
        if (c + PIPE < NTILES)
            issue_tile(c + PIPE, stage);
    }
}

// ---------------------------------------------------------------------------
extern "C" void kernel_launch(void* const* d_in, const int* in_sizes, int n_in,
                              void* d_out, int out_size)
{
    const float* inputs = (const float*)d_in[0];  // [64,1024,256]
    const float* w      = (const float*)d_in[1];  // [256,256]
    float* out          = (float*)d_out;          // [64,1024,256]

    const int M = 64 * 1024;   // 65536
    const int N = 256;
    const int K = 256;

    // Stage 1: x = inputs @ w  -> d_out
    dim3 gemmGrid(N / cfg::BN, M / cfg::BM);   // (2, 512)
    sgemm_kernel<<<gemmGrid, 256>>>(inputs, w, out, M, N, K);

    // Stage 2: in-place scan x -> U  (128 blocks = 64 batches x 2 halves)
    lif_scan_kernel<<<64 * 2, LPB>>>(out);
}

// round 10
// speedup vs baseline: 2.1708x; 1.4614x over previous
#include <cuda_runtime.h>
#include <cstdint>

// LIF spiking layer, monitor='mem'
//   inputs: [B=64, T=1024, IN=256] f32   (d_in[0])
//   w:      [IN=256, OUT=256] f32        (d_in[1])
//   out U:  [B=64, T=1024, OUT=256] f32  (d_out)
//
// compute_103 target: tcgen05 unavailable -> use portable mma.sync HMMA.
// Stage 0: prep — split W into 2 tf32 limbs, packed in B-fragment order.
// Stage 1: 3xTF32 GEMM (mma.sync.m16n8k8): x = inputs @ w -> d_out.
// Stage 2: in-place LIF scan (cp.async double-buffered), x -> U. (unchanged)

// ---------------------------------------------------------------------------
// helpers
// ---------------------------------------------------------------------------
__device__ __forceinline__ void cp_async16(uint32_t smem_addr, const void* gptr) {
    asm volatile("cp.async.cg.shared.global [%0], [%1], 16;"
                 :: "r"(smem_addr), "l"(gptr) : "memory");
}
__device__ __forceinline__ void cp_async_commit() {
    asm volatile("cp.async.commit_group;" ::: "memory");
}
template <int N>
__device__ __forceinline__ void cp_async_wait() {
    asm volatile("cp.async.wait_group %0;" :: "n"(N) : "memory");
}
__device__ __forceinline__ uint32_t smem_u32(const void* p) {
    uint32_t a;
    asm("{ .reg .u64 t; cvta.to.shared.u64 t, %1; cvt.u32.u64 %0, t; }"
        : "=r"(a) : "l"(p));
    return a;
}
__device__ __forceinline__ uint32_t f32_to_tf32(float f) {
    uint32_t u;
    asm("cvt.rna.tf32.f32 %0, %1;" : "=r"(u) : "f"(f));
    return u;
}
__device__ __forceinline__ void mma_tf32(float* c, const uint32_t* a,
                                         uint32_t b0, uint32_t b1) {
    asm volatile(
        "mma.sync.aligned.m16n8k8.row.col.f32.tf32.tf32.f32 "
        "{%0,%1,%2,%3}, {%4,%5,%6,%7}, {%8,%9}, {%0,%1,%2,%3};"
        : "+f"(c[0]), "+f"(c[1]), "+f"(c[2]), "+f"(c[3])
        : "r"(a[0]), "r"(a[1]), "r"(a[2]), "r"(a[3]), "r"(b0), "r"(b1));
}

// B fragments: [h(2)][nt(16)][ks(32)][lane(32)][l0b0,l0b1,l1b0,l1b1] = 512KB
__device__ __align__(16) uint32_t g_Bfrag[2 * 16 * 32 * 32 * 4];

// ---------------------------------------------------------------------------
// Stage 0: W -> tf32 limb fragments.
// mma m16n8k8 B layout: g = lane>>2, t = lane&3; b0=(k=t,n=g), b1=(k=t+4,n=g)
// ---------------------------------------------------------------------------
__global__ void prep_w_kernel(const float* __restrict__ w) {
    int idx = blockIdx.x * blockDim.x + threadIdx.x;  // 0..65535
    int k = idx >> 8;
    int n = idx & 255;
    float v = w[k * 256 + n];
    uint32_t u0 = f32_to_tf32(v);
    uint32_t u1 = f32_to_tf32(v - __uint_as_float(u0));

    int h = n >> 7, n_ = n & 127;
    int nt = n_ >> 3, g = n_ & 7;
    int ks = k >> 3, r = k & 7;
    int t = r & 3, reg = r >> 2;
    int lane = g * 4 + t;
    int base = (((h * 16 + nt) * 32 + ks) * 32 + lane) * 4;
    g_Bfrag[base + 0 + reg] = u0;   // limb0: b0,b1
    g_Bfrag[base + 2 + reg] = u1;   // limb1: b0,b1
}

// ---------------------------------------------------------------------------
// Stage 1: 3xTF32 GEMM. Grid 1024 = 512 mtiles x 2 n-halves. 256 threads.
// smem per stage: A 32KB (8 mt x 4 ksl x [limb(2) x lane(32) x 16B])
//                 B 32KB (16 nt x 4 ksl x lane x 16B)
// double buffered -> 128KB.
// ---------------------------------------------------------------------------
constexpr int STAGE_BYTES = 65536;
constexpr int A_BYTES     = 32768;
constexpr int GEMM_SMEM   = 2 * STAGE_BYTES;

struct ARegs { float4 lo[2], hi[2]; };  // two tasks x (row r, row r+8)

__device__ __forceinline__ void ldA(const float* __restrict__ A, int mtile,
                                    int s, int tid, ARegs& rg) {
#pragma unroll
    for (int q = 0; q < 2; ++q) {
        int tau = tid + q * 256;         // 0..511
        int cc  = tau & 7;               // col chunk (4 floats)
        int pid = tau >> 3;              // 0..63
        int mtg = pid >> 3, g = pid & 7;
        const float* p = A + (size_t)(mtile * 128 + mtg * 16 + g) * 256 + s * 32 + cc * 4;
        rg.lo[q] = *(const float4*)p;
        rg.hi[q] = *(const float4*)(p + 8 * 256);
    }
}

__device__ __forceinline__ void stA(char* abuf, int tid, const ARegs& rg) {
#pragma unroll
    for (int q = 0; q < 2; ++q) {
        int tau = tid + q * 256;
        int cc  = tau & 7;
        int pid = tau >> 3;
        int mtg = pid >> 3, g = pid & 7;
        int ksl = cc >> 1;
        int high = (cc & 1) * 8;
        const float* lo = (const float*)&rg.lo[q];
        const float* hi = (const float*)&rg.hi[q];
        char* blk = abuf + (mtg * 4 + ksl) * 1024;
#pragma unroll
        for (int t = 0; t < 4; ++t) {
            float va = lo[t], vb = hi[t];
            uint32_t a0 = f32_to_tf32(va);
            uint32_t a1 = f32_to_tf32(va - __uint_as_float(a0));
            uint32_t c0 = f32_to_tf32(vb);
            uint32_t c1 = f32_to_tf32(vb - __uint_as_float(c0));
            int lane = g * 4 + t;
            // limb0 pair (a0-slot, a1-slot), limb1 pair
            *(uint2*)(blk + 0   + lane * 16 + high) = make_uint2(a0, c0);
            *(uint2*)(blk + 512 + lane * 16 + high) = make_uint2(a1, c1);
        }
    }
}

__device__ __forceinline__ void cpB(uint32_t bbuf, int h, int s, int tid) {
    const uint32_t* src = g_Bfrag + (size_t)h * (16 * 32 * 32 * 4);
#pragma unroll
    for (int i = 0; i < 8; ++i) {
        int q = tid + i * 256;           // 0..2047: ((nt*4+ksl)*32+lane)
        int lane = q & 31;
        int ksl  = (q >> 5) & 3;
        int nt   = q >> 7;
        const uint32_t* g = src + ((nt * 32 + s * 4 + ksl) * 32 + lane) * 4;
        cp_async16(bbuf + q * 16, g);
    }
    cp_async_commit();
}

__global__ __launch_bounds__(256) void gemm_tc_kernel(
    const float* __restrict__ A, float* __restrict__ out)
{
    extern __shared__ char smem[];
    const int tid    = threadIdx.x;
    const int wid    = tid >> 5;
    const int lane   = tid & 31;
    const int warp_m = wid & 3;        // 4 x 32 rows
    const int warp_n = wid >> 2;       // 2 x 64 cols
    const int mtile  = blockIdx.x >> 1;
    const int h      = blockIdx.x & 1;

    const uint32_t sbase = smem_u32(smem);

    float acc[2][8][4];
#pragma unroll
    for (int i = 0; i < 2; ++i)
#pragma unroll
        for (int j = 0; j < 8; ++j)
#pragma unroll
            for (int k = 0; k < 4; ++k) acc[i][j][k] = 0.0f;

    ARegs rg;
    // prologue: stage 0
    cpB(sbase + A_BYTES, h, 0, tid);
    ldA(A, mtile, 0, tid, rg);
    stA(smem, tid, rg);
    cp_async_wait<0>();
    __syncthreads();

    for (int s = 0; s < 8; ++s) {
        const int buf = s & 1;
        char* cbuf = smem + buf * STAGE_BYTES;
        char* nbuf = smem + (buf ^ 1) * STAGE_BYTES;

        if (s < 7) {
            cpB(sbase + (buf ^ 1) * STAGE_BYTES + A_BYTES, h, s + 1, tid);
            ldA(A, mtile, s + 1, tid, rg);
        }

#pragma unroll
        for (int ksl = 0; ksl < 4; ++ksl) {
            uint32_t af[2][2][4];
#pragma unroll
            for (int mtl = 0; mtl < 2; ++mtl) {
                int mtg = warp_m * 2 + mtl;
                char* blk = cbuf + (mtg * 4 + ksl) * 1024;
                *(uint4*)af[mtl][0] = *(uint4*)(blk + 0   + lane * 16);
                *(uint4*)af[mtl][1] = *(uint4*)(blk + 512 + lane * 16);
            }
            uint32_t bf[8][4];
#pragma unroll
            for (int ntl = 0; ntl < 8; ++ntl) {
                int nt = warp_n * 8 + ntl;
                *(uint4*)bf[ntl] =
                    *(uint4*)(cbuf + A_BYTES + ((nt * 4 + ksl) * 32 + lane) * 16);
            }
#pragma unroll
            for (int mtl = 0; mtl < 2; ++mtl)
#pragma unroll
                for (int ntl = 0; ntl < 8; ++ntl) {
                    mma_tf32(acc[mtl][ntl], af[mtl][0], bf[ntl][0], bf[ntl][1]); // a0*b0
                    mma_tf32(acc[mtl][ntl], af[mtl][0], bf[ntl][2], bf[ntl][3]); // a0*b1
                    mma_tf32(acc[mtl][ntl], af[mtl][1], bf[ntl][0], bf[ntl][1]); // a1*b0
                }
        }

        if (s < 7) {
            stA(nbuf, tid, rg);
            cp_async_wait<0>();
        }
        __syncthreads();
    }

    // epilogue: c0=(g,2t) c1=(g,2t+1) c2=(g+8,2t) c3=(g+8,2t+1)
    const int g = lane >> 2, t = lane & 3;
#pragma unroll
    for (int mtl = 0; mtl < 2; ++mtl) {
        int row0 = mtile * 128 + warp_m * 32 + mtl * 16 + g;
#pragma unroll
        for (int ntl = 0; ntl < 8; ++ntl) {
            int col = h * 128 + warp_n * 64 + ntl * 8 + 2 * t;
            *(float2*)(out + (size_t)row0 * 256 + col) =
                make_float2(acc[mtl][ntl][0], acc[mtl][ntl][1]);
            *(float2*)(out + (size_t)(row0 + 8) * 256 + col) =
                make_float2(acc[mtl][ntl][2], acc[mtl][ntl][3]);
        }
    }
}

// ---------------------------------------------------------------------------
// Stage 2: in-place LIF scan (unchanged — 28.8us, bit-exact)
// ---------------------------------------------------------------------------
constexpr int T_STEPS = 1024;
constexpr int OUT_C   = 256;
constexpr int TS      = 32;
constexpr int LPB     = 128;
constexpr int NTILES  = T_STEPS / TS;
constexpr int PIPE    = 2;

__global__ __launch_bounds__(LPB) void lif_scan_kernel(float* __restrict__ X)
{
    __shared__ float tile[PIPE][TS * LPB];

    const int tid  = threadIdx.x;
    const int b    = blockIdx.x >> 1;
    const int half = blockIdx.x & 1;
    float* base  = X + (size_t)b * T_STEPS * OUT_C + half * LPB;
    float* gbase = base + tid;

    uint32_t smem_base = smem_u32(&tile[0][0]);

    auto issue_tile = [&](int c, int stage) {
#pragma unroll
        for (int k = 0; k < 8; ++k) {
            int chunk = tid + k * LPB;
            int row   = chunk >> 5;
            int c16   = chunk & 31;
            const void* g = (const char*)base +
                (size_t)(c * TS + row) * OUT_C * 4 + c16 * 16;
            uint32_t s = smem_base + stage * (TS * LPB * 4) + row * (LPB * 4) + c16 * 16;
            cp_async16(s, g);
        }
        cp_async_commit();
    };

    issue_tile(0, 0);
    issue_tile(1, 1);

    const float dcy_syn = 0.81873075307798185867f;   // exp(-0.2)
    const float dcy_mem = 0.90483741803595957316f;   // exp(-0.1)
    const float scl_mem = 1.0f - dcy_mem;

    float syn = 0.0f, mem = 0.0f;
    float carry = 0.0f;

    for (int c = 0; c < NTILES; ++c) {
        const int stage = c & (PIPE - 1);
        if (c == NTILES - 1) cp_async_wait<0>();
        else                 cp_async_wait<PIPE - 1>();
        __syncthreads();

        gbase[(size_t)(c * TS) * OUT_C] = carry;

        const float* sm = &tile[stage][tid];
#pragma unroll
        for (int i = 0; i < TS; ++i) {
            const int t = c * TS + i;
            if (t < T_STEPS - 1) {
                const float x    = sm[i * LPB];
                const float nsyn = fmaf(dcy_syn, syn, x);
                float nmem = fmaf(dcy_mem, mem, scl_mem * syn);
                if (mem > 1.0f) nmem = 0.0f;
                if (i < TS - 1)
                    gbase[(size_t)(t + 1) * OUT_C] = nmem;
                else
                    carry = nmem;
                syn = nsyn;
                mem = nmem;
            }
        }

        __syncthreads();
        if (c + PIPE < NTILES)
            issue_tile(c + PIPE, stage);
    }
}

// ---------------------------------------------------------------------------
extern "C" void kernel_launch(void* const* d_in, const int* in_sizes, int n_in,
                              void* d_out, int out_size)
{
    const float* inputs = (const float*)d_in[0];  // [64,1024,256]
    const float* w      = (const float*)d_in[1];  // [256,256]
    float* out          = (float*)d_out;          // [64,1024,256]

    cudaFuncSetAttribute(gemm_tc_kernel,
                         cudaFuncAttributeMaxDynamicSharedMemorySize, GEMM_SMEM);

    // Stage 0: W -> tf32 limb fragments
    prep_w_kernel<<<256, 256>>>(w);

    // Stage 1: x = inputs @ w -> d_out (3xTF32 mma.sync)
    gemm_tc_kernel<<<1024, 256, GEMM_SMEM>>>(inputs, out);

    // Stage 2: in-place scan x -> U
    lif_scan_kernel<<<64 * 2, LPB>>>(out);
}

// round 11
// speedup vs baseline: 3.3295x; 1.5338x over previous
#include <cuda_runtime.h>
#include <cuda_fp16.h>
#include <cstdint>

// LIF spiking layer, monitor='mem'
//   inputs: [B=64, T=1024, IN=256] f32   (d_in[0])
//   w:      [IN=256, OUT=256] f32        (d_in[1])
//   out U:  [B=64, T=1024, OUT=256] f32  (d_out)
//
// compute_103 target: tcgen05 unavailable -> portable mma.sync HMMA.
// Stage 0: prep — split W into 2 fp16 limbs, packed in m16n8k16 B-fragment order.
// Stage 1: 3xFP16 GEMM (mma.sync.m16n8k16, f32 accum): x = inputs @ w -> d_out.
//          a0b0 + a0b1 + a1b0, dropped a1b1 ~2^-22 (same accuracy as 3xTF32).
// Stage 2: in-place LIF scan (cp.async double-buffered), x -> U. (unchanged)

// ---------------------------------------------------------------------------
// helpers
// ---------------------------------------------------------------------------
__device__ __forceinline__ void cp_async16(uint32_t smem_addr, const void* gptr) {
    asm volatile("cp.async.cg.shared.global [%0], [%1], 16;"
                 :: "r"(smem_addr), "l"(gptr) : "memory");
}
__device__ __forceinline__ void cp_async_commit() {
    asm volatile("cp.async.commit_group;" ::: "memory");
}
template <int N>
__device__ __forceinline__ void cp_async_wait() {
    asm volatile("cp.async.wait_group %0;" :: "n"(N) : "memory");
}
__device__ __forceinline__ uint32_t smem_u32(const void* p) {
    uint32_t a;
    asm("{ .reg .u64 t; cvta.to.shared.u64 t, %1; cvt.u32.u64 %0, t; }"
        : "=r"(a) : "l"(p));
    return a;
}
__device__ __forceinline__ void mma_f16(float* c, const uint32_t* a,
                                        uint32_t b0, uint32_t b1) {
    asm volatile(
        "mma.sync.aligned.m16n8k16.row.col.f32.f16.f16.f32 "
        "{%0,%1,%2,%3}, {%4,%5,%6,%7}, {%8,%9}, {%0,%1,%2,%3};"
        : "+f"(c[0]), "+f"(c[1]), "+f"(c[2]), "+f"(c[3])
        : "r"(a[0]), "r"(a[1]), "r"(a[2]), "r"(a[3]), "r"(b0), "r"(b1));
}

// B fragments: [h(2)][nt(16)][k16(16)][lane(32)][l0b0,l0b1,l1b0,l1b1] = 256KB
__device__ __align__(16) unsigned char g_Bfrag[2 * 16 * 16 * 32 * 16];

// ---------------------------------------------------------------------------
// Stage 0: W -> fp16 limb fragments, m16n8k16 B layout (col-major B):
//   lane = g*4 + t (g = n&7, t from k): b0 holds (k=2t, 2t+1, n=g),
//   b1 holds (k=2t+8, 2t+9, n=g). reg = (k&8)>>3 selects b0/b1, k&1 the half.
// ---------------------------------------------------------------------------
__global__ void prep_w_kernel(const float* __restrict__ w) {
    int idx = blockIdx.x * blockDim.x + threadIdx.x;  // 0..65535
    int k = idx >> 8;
    int n = idx & 255;
    float v = w[k * 256 + n];
    __half h0 = __float2half_rn(v);
    __half h1 = __float2half_rn(v - __half2float(h0));

    int h = n >> 7, n_ = n & 127;
    int nt = n_ >> 3, g = n_ & 7;
    int k16 = k >> 4, kk = k & 15;
    int t = (kk & 7) >> 1;
    int reg = (kk & 8) >> 3;
    int hs = kk & 1;
    int lane = g * 4 + t;
    unsigned char* base =
        &g_Bfrag[((((size_t)h * 16 + nt) * 16 + k16) * 32 + lane) * 16];
    *(__half*)(base + reg * 4 + hs * 2)     = h0;   // limb0: b0,b1
    *(__half*)(base + 8 + reg * 4 + hs * 2) = h1;   // limb1: b0,b1
}

// ---------------------------------------------------------------------------
// Stage 1: 3xFP16 GEMM. Grid 1024 = 512 mtiles x 2 n-halves. 256 threads.
// Per stage (BK=32): A 16KB (8 mtg x 2 k16 x [limb(2) x lane(32) x 16B]),
//                    B 16KB (16 nt x 2 k16 x lane x 16B). Double buffer 64KB.
// ---------------------------------------------------------------------------
constexpr int A_STAGE     = 16384;
constexpr int STAGE_BYTES = 32768;
constexpr int GEMM_SMEM   = 2 * STAGE_BYTES;   // 64KB

struct ARegs { float4 lo[2], hi[2]; };  // two tasks x (row g, row g+8)

__device__ __forceinline__ void ldA(const float* __restrict__ A, int mtile,
                                    int s, int tid, ARegs& rg) {
#pragma unroll
    for (int q = 0; q < 2; ++q) {
        int tau = tid + q * 256;         // 0..511
        int cc  = tau & 7;               // col chunk (4 floats within 32-col stage)
        int pid = tau >> 3;              // 0..63
        int mtg = pid >> 3, g = pid & 7;
        const float* p = A + (size_t)(mtile * 128 + mtg * 16 + g) * 256 + s * 32 + cc * 4;
        rg.lo[q] = *(const float4*)p;
        rg.hi[q] = *(const float4*)(p + 8 * 256);
    }
}

// A-fragment layout per (mtg,k16) block (1024B): limb0 lanes [0,512),
// limb1 [512,1024); per lane 16B = [a0 a1 a2 a3]:
//   a0=(g, 2t..2t+1) k<8, a1=(g+8, ...), a2/a3 same for k>=8.
__device__ __forceinline__ void stA(char* abuf, int tid, const ARegs& rg) {
#pragma unroll
    for (int q = 0; q < 2; ++q) {
        int tau = tid + q * 256;
        int cc  = tau & 7;
        int pid = tau >> 3;
        int mtg = pid >> 3, g = pid & 7;
        int k16l = cc >> 2;              // which k16 within stage
        int kk0  = (cc & 3) * 4;         // k offset within k16
        char* blk = abuf + (mtg * 2 + k16l) * 1024;
        const float* lo = (const float*)&rg.lo[q];
        const float* hi = (const float*)&rg.hi[q];
#pragma unroll
        for (int p = 0; p < 2; ++p) {
            int kk = kk0 + 2 * p;
            int t = (kk & 7) >> 1;
            int koff = kk & 8;           // 0 -> a0/a1 slot, 8 -> a2/a3 slot
            int lane = g * 4 + t;
            float v00 = lo[2 * p], v01 = lo[2 * p + 1];
            float v10 = hi[2 * p], v11 = hi[2 * p + 1];
            __half a00 = __float2half_rn(v00), a01 = __float2half_rn(v01);
            __half a10 = __float2half_rn(v10), a11 = __float2half_rn(v11);
            __half b00 = __float2half_rn(v00 - __half2float(a00));
            __half b01 = __float2half_rn(v01 - __half2float(a01));
            __half b10 = __float2half_rn(v10 - __half2float(a10));
            __half b11 = __float2half_rn(v11 - __half2float(a11));
            __half2 l0g  = __halves2half2(a00, a01);   // row g,   limb0
            __half2 l0g8 = __halves2half2(a10, a11);   // row g+8, limb0
            __half2 l1g  = __halves2half2(b00, b01);
            __half2 l1g8 = __halves2half2(b10, b11);
            *(uint2*)(blk + lane * 16 + koff) =
                make_uint2(*(uint32_t*)&l0g, *(uint32_t*)&l0g8);
            *(uint2*)(blk + 512 + lane * 16 + koff) =
                make_uint2(*(uint32_t*)&l1g, *(uint32_t*)&l1g8);
        }
    }
}

__device__ __forceinline__ void cpB(uint32_t bbuf, int h, int s, int tid) {
#pragma unroll
    for (int i = 0; i < 4; ++i) {
        int q = tid + i * 256;           // 0..1023: nt*64 + k16l*32 + lane
        int lane = q & 31;
        int k16l = (q >> 5) & 1;
        int nt   = q >> 6;
        const unsigned char* src =
            g_Bfrag + ((((size_t)h * 16 + nt) * 16 + (2 * s + k16l)) * 32 + lane) * 16;
        cp_async16(bbuf + q * 16, src);
    }
    cp_async_commit();
}

__global__ __launch_bounds__(256) void gemm_tc_kernel(
    const float* __restrict__ A, float* __restrict__ out)
{
    extern __shared__ char smem[];
    const int tid    = threadIdx.x;
    const int wid    = tid >> 5;
    const int lane   = tid & 31;
    const int warp_m = wid & 3;        // 4 x 32 rows
    const int warp_n = wid >> 2;       // 2 x 64 cols
    const int mtile  = blockIdx.x >> 1;
    const int h      = blockIdx.x & 1;

    const uint32_t sbase = smem_u32(smem);

    float acc[2][8][4];
#pragma unroll
    for (int i = 0; i < 2; ++i)
#pragma unroll
        for (int j = 0; j < 8; ++j)
#pragma unroll
            for (int k = 0; k < 4; ++k) acc[i][j][k] = 0.0f;

    ARegs rg;
    // prologue: stage 0
    cpB(sbase + A_STAGE, h, 0, tid);
    ldA(A, mtile, 0, tid, rg);
    stA(smem, tid, rg);
    cp_async_wait<0>();
    __syncthreads();

    for (int s = 0; s < 8; ++s) {
        const int buf = s & 1;
        char* cbuf = smem + buf * STAGE_BYTES;
        char* nbuf = smem + (buf ^ 1) * STAGE_BYTES;

        if (s < 7) {
            cpB(sbase + (buf ^ 1) * STAGE_BYTES + A_STAGE, h, s + 1, tid);
            ldA(A, mtile, s + 1, tid, rg);
        }

#pragma unroll
        for (int k16l = 0; k16l < 2; ++k16l) {
            uint4 afr[2][2];
#pragma unroll
            for (int mtl = 0; mtl < 2; ++mtl) {
                int mtg = warp_m * 2 + mtl;
                char* blk = cbuf + (mtg * 2 + k16l) * 1024;
                afr[mtl][0] = *(uint4*)(blk + lane * 16);
                afr[mtl][1] = *(uint4*)(blk + 512 + lane * 16);
            }
            uint4 bfr[8];
#pragma unroll
            for (int ntl = 0; ntl < 8; ++ntl) {
                int nt = warp_n * 8 + ntl;
                bfr[ntl] = *(uint4*)(cbuf + A_STAGE +
                                     ((nt * 2 + k16l) * 32 + lane) * 16);
            }
#pragma unroll
            for (int mtl = 0; mtl < 2; ++mtl)
#pragma unroll
                for (int ntl = 0; ntl < 8; ++ntl) {
                    mma_f16(acc[mtl][ntl], (const uint32_t*)&afr[mtl][0],
                            bfr[ntl].x, bfr[ntl].y);               // a0*b0
                    mma_f16(acc[mtl][ntl], (const uint32_t*)&afr[mtl][0],
                            bfr[ntl].z, bfr[ntl].w);               // a0*b1
                    mma_f16(acc[mtl][ntl], (const uint32_t*)&afr[mtl][1],
                            bfr[ntl].x, bfr[ntl].y);               // a1*b0
                }
        }

        if (s < 7) {
            stA(nbuf, tid, rg);
            cp_async_wait<0>();
        }
        __syncthreads();
    }

    // epilogue: c0=(g,2t) c1=(g,2t+1) c2=(g+8,2t) c3=(g+8,2t+1)
    const int g = lane >> 2, t = lane & 3;
#pragma unroll
    for (int mtl = 0; mtl < 2; ++mtl) {
        int row0 = mtile * 128 + warp_m * 32 + mtl * 16 + g;
#pragma unroll
        for (int ntl = 0; ntl < 8; ++ntl) {
            int col = h * 128 + warp_n * 64 + ntl * 8 + 2 * t;
            *(float2*)(out + (size_t)row0 * 256 + col) =
                make_float2(acc[mtl][ntl][0], acc[mtl][ntl][1]);
            *(float2*)(out + (size_t)(row0 + 8) * 256 + col) =
                make_float2(acc[mtl][ntl][2], acc[mtl][ntl][3]);
        }
    }
}

// ---------------------------------------------------------------------------
// Stage 2: in-place LIF scan (unchanged — 28.8us)
// ---------------------------------------------------------------------------
constexpr int T_STEPS = 1024;
constexpr int OUT_C   = 256;
constexpr int TS      = 32;
constexpr int LPB     = 128;
constexpr int NTILES  = T_STEPS / TS;
constexpr int PIPE    = 2;

__global__ __launch_bounds__(LPB) void lif_scan_kernel(float* __restrict__ X)
{
    __shared__ float tile[PIPE][TS * LPB];

    const int tid  = threadIdx.x;
    const int b    = blockIdx.x >> 1;
    const int half = blockIdx.x & 1;
    float* base  = X + (size_t)b * T_STEPS * OUT_C + half * LPB;
    float* gbase = base + tid;

    uint32_t smem_base = smem_u32(&tile[0][0]);

    auto issue_tile = [&](int c, int stage) {
#pragma unroll
        for (int k = 0; k < 8; ++k) {
            int chunk = tid + k * LPB;
            int row   = chunk >> 5;
            int c16   = chunk & 31;
            const void* g = (const char*)base +
                (size_t)(c * TS + row) * OUT_C * 4 + c16 * 16;
            uint32_t s = smem_base + stage * (TS * LPB * 4) + row * (LPB * 4) + c16 * 16;
            cp_async16(s, g);
        }
        cp_async_commit();
    };

    issue_tile(0, 0);
    issue_tile(1, 1);

    const float dcy_syn = 0.81873075307798185867f;   // exp(-0.2)
    const float dcy_mem = 0.90483741803595957316f;   // exp(-0.1)
    const float scl_mem = 1.0f - dcy_mem;

    float syn = 0.0f, mem = 0.0f;
    float carry = 0.0f;

    for (int c = 0; c < NTILES; ++c) {
        const int stage = c & (PIPE - 1);
        if (c == NTILES - 1) cp_async_wait<0>();
        else                 cp_async_wait<PIPE - 1>();
        __syncthreads();

        gbase[(size_t)(c * TS) * OUT_C] = carry;

        const float* sm = &tile[stage][tid];
#pragma unroll
        for (int i = 0; i < TS; ++i) {
            const int t = c * TS + i;
            if (t < T_STEPS - 1) {
                const float x    = sm[i * LPB];
                const float nsyn = fmaf(dcy_syn, syn, x);
                float nmem = fmaf(dcy_mem, mem, scl_mem * syn);
                if (mem > 1.0f) nmem = 0.0f;
                if (i < TS - 1)
                    gbase[(size_t)(t + 1) * OUT_C] = nmem;
                else
                    carry = nmem;
                syn = nsyn;
                mem = nmem;
            }
        }

        __syncthreads();
        if (c + PIPE < NTILES)
            issue_tile(c + PIPE, stage);
    }
}

// ---------------------------------------------------------------------------
extern "C" void kernel_launch(void* const* d_in, const int* in_sizes, int n_in,
                              void* d_out, int out_size)
{
    const float* inputs = (const float*)d_in[0];  // [64,1024,256]
    const float* w      = (const float*)d_in[1];  // [256,256]
    float* out          = (float*)d_out;          // [64,1024,256]

    cudaFuncSetAttribute(gemm_tc_kernel,
                         cudaFuncAttributeMaxDynamicSharedMemorySize, GEMM_SMEM);

    // Stage 0: W -> fp16 limb fragments
    prep_w_kernel<<<256, 256>>>(w);

    // Stage 1: x = inputs @ w -> d_out (3xFP16 mma.sync m16n8k16)
    gemm_tc_kernel<<<1024, 256, GEMM_SMEM>>>(inputs, out);

    // Stage 2: in-place scan x -> U
    lif_scan_kernel<<<64 * 2, LPB>>>(out);
}

// round 12
// speedup vs baseline: 3.3965x; 1.0201x over previous
#include <cuda_runtime.h>
#include <cuda_fp16.h>
#include <cstdint>

// LIF spiking layer, monitor='mem'
//   inputs: [B=64, T=1024, IN=256] f32   (d_in[0])
//   w:      [IN=256, OUT=256] f32        (d_in[1])
//   out U:  [B=64, T=1024, OUT=256] f32  (d_out)
//
// Stage 0: prep — split W into 2 fp16 limbs, packed in m16n8k16 B-fragment order.
// Stage 1: 3xFP16 GEMM (mma.sync.m16n8k16, f32 accum), 3-stage pipeline,
//          2 CTAs/SM: x = inputs @ w -> d_out.
// Stage 2: in-place LIF scan, 256 CTAs x 64 threads.

// ---------------------------------------------------------------------------
// helpers
// ---------------------------------------------------------------------------
__device__ __forceinline__ void cp_async16(uint32_t smem_addr, const void* gptr) {
    asm volatile("cp.async.cg.shared.global [%0], [%1], 16;"
                 :: "r"(smem_addr), "l"(gptr) : "memory");
}
__device__ __forceinline__ void cp_async_commit() {
    asm volatile("cp.async.commit_group;" ::: "memory");
}
template <int N>
__device__ __forceinline__ void cp_async_wait() {
    asm volatile("cp.async.wait_group %0;" :: "n"(N) : "memory");
}
__device__ __forceinline__ uint32_t smem_u32(const void* p) {
    uint32_t a;
    asm("{ .reg .u64 t; cvta.to.shared.u64 t, %1; cvt.u32.u64 %0, t; }"
        : "=r"(a) : "l"(p));
    return a;
}
__device__ __forceinline__ void mma_f16(float* c, const uint32_t* a,
                                        uint32_t b0, uint32_t b1) {
    asm volatile(
        "mma.sync.aligned.m16n8k16.row.col.f32.f16.f16.f32 "
        "{%0,%1,%2,%3}, {%4,%5,%6,%7}, {%8,%9}, {%0,%1,%2,%3};"
        : "+f"(c[0]), "+f"(c[1]), "+f"(c[2]), "+f"(c[3])
        : "r"(a[0]), "r"(a[1]), "r"(a[2]), "r"(a[3]), "r"(b0), "r"(b1));
}

// B fragments: [h(2)][nt(16)][k16(16)][lane(32)][l0b0,l0b1,l1b0,l1b1] = 256KB
__device__ __align__(16) unsigned char g_Bfrag[2 * 16 * 16 * 32 * 16];

// ---------------------------------------------------------------------------
// Stage 0: W -> fp16 limb fragments (m16n8k16 B layout, col-major B).
// ---------------------------------------------------------------------------
__global__ void prep_w_kernel(const float* __restrict__ w) {
    int idx = blockIdx.x * blockDim.x + threadIdx.x;  // 0..65535
    int k = idx >> 8;
    int n = idx & 255;
    float v = w[k * 256 + n];
    __half h0 = __float2half_rn(v);
    __half h1 = __float2half_rn(v - __half2float(h0));

    int h = n >> 7, n_ = n & 127;
    int nt = n_ >> 3, g = n_ & 7;
    int k16 = k >> 4, kk = k & 15;
    int t = (kk & 7) >> 1;
    int reg = (kk & 8) >> 3;
    int hs = kk & 1;
    int lane = g * 4 + t;
    unsigned char* base =
        &g_Bfrag[((((size_t)h * 16 + nt) * 16 + k16) * 32 + lane) * 16];
    *(__half*)(base + reg * 4 + hs * 2)     = h0;   // limb0: b0,b1
    *(__half*)(base + 8 + reg * 4 + hs * 2) = h1;   // limb1: b0,b1
}

// ---------------------------------------------------------------------------
// Stage 1: 3xFP16 GEMM. Grid 1024 = 512 mtiles x 2 n-halves. 256 threads.
// Per stage (BK=32): A 16KB (8 mtg x 2 k16 x [limb(2) x lane(32) x 16B]),
//                    B 16KB (16 nt x 2 k16 x lane x 16B).
// 3-stage circular buffer (96KB), 2 CTAs/SM.
// ---------------------------------------------------------------------------
constexpr int A_STAGE     = 16384;
constexpr int STAGE_BYTES = 32768;
constexpr int NSTAGE      = 3;
constexpr int GEMM_SMEM   = NSTAGE * STAGE_BYTES;   // 96KB

struct ARegs { float4 lo[2], hi[2]; };  // two tasks x (row g, row g+8)

__device__ __forceinline__ void ldA(const float* __restrict__ A, int mtile,
                                    int s, int tid, ARegs& rg) {
#pragma unroll
    for (int q = 0; q < 2; ++q) {
        int tau = tid + q * 256;         // 0..511
        int cc  = tau & 7;               // col chunk (4 floats within 32-col stage)
        int pid = tau >> 3;              // 0..63
        int mtg = pid >> 3, g = pid & 7;
        const float* p = A + (size_t)(mtile * 128 + mtg * 16 + g) * 256 + s * 32 + cc * 4;
        rg.lo[q] = *(const float4*)p;
        rg.hi[q] = *(const float4*)(p + 8 * 256);
    }
}

__device__ __forceinline__ void stA(char* abuf, int tid, const ARegs& rg) {
#pragma unroll
    for (int q = 0; q < 2; ++q) {
        int tau = tid + q * 256;
        int cc  = tau & 7;
        int pid = tau >> 3;
        int mtg = pid >> 3, g = pid & 7;
        int k16l = cc >> 2;              // which k16 within stage
        int kk0  = (cc & 3) * 4;         // k offset within k16
        char* blk = abuf + (mtg * 2 + k16l) * 1024;
        const float* lo = (const float*)&rg.lo[q];
        const float* hi = (const float*)&rg.hi[q];
#pragma unroll
        for (int p = 0; p < 2; ++p) {
            int kk = kk0 + 2 * p;
            int t = (kk & 7) >> 1;
            int koff = kk & 8;           // 0 -> a0/a1 slot, 8 -> a2/a3 slot
            int lane = g * 4 + t;
            float v00 = lo[2 * p], v01 = lo[2 * p + 1];
            float v10 = hi[2 * p], v11 = hi[2 * p + 1];
            __half a00 = __float2half_rn(v00), a01 = __float2half_rn(v01);
            __half a10 = __float2half_rn(v10), a11 = __float2half_rn(v11);
            __half b00 = __float2half_rn(v00 - __half2float(a00));
            __half b01 = __float2half_rn(v01 - __half2float(a01));
            __half b10 = __float2half_rn(v10 - __half2float(a10));
            __half b11 = __float2half_rn(v11 - __half2float(a11));
            __half2 l0g  = __halves2half2(a00, a01);
            __half2 l0g8 = __halves2half2(a10, a11);
            __half2 l1g  = __halves2half2(b00, b01);
            __half2 l1g8 = __halves2half2(b10, b11);
            *(uint2*)(blk + lane * 16 + koff) =
                make_uint2(*(uint32_t*)&l0g, *(uint32_t*)&l0g8);
            *(uint2*)(blk + 512 + lane * 16 + koff) =
                make_uint2(*(uint32_t*)&l1g, *(uint32_t*)&l1g8);
        }
    }
}

__device__ __forceinline__ void cpB(uint32_t bbuf, int h, int s, int tid) {
#pragma unroll
    for (int i = 0; i < 4; ++i) {
        int q = tid + i * 256;           // 0..1023: nt*64 + k16l*32 + lane
        int lane = q & 31;
        int k16l = (q >> 5) & 1;
        int nt   = q >> 6;
        const unsigned char* src =
            g_Bfrag + ((((size_t)h * 16 + nt) * 16 + (2 * s + k16l)) * 32 + lane) * 16;
        cp_async16(bbuf + q * 16, src);
    }
    cp_async_commit();
}

__global__ __launch_bounds__(256, 2) void gemm_tc_kernel(
    const float* __restrict__ A, float* __restrict__ out)
{
    extern __shared__ char smem[];
    const int tid    = threadIdx.x;
    const int wid    = tid >> 5;
    const int lane   = tid & 31;
    const int warp_m = wid & 3;        // 4 x 32 rows
    const int warp_n = wid >> 2;       // 2 x 64 cols
    const int mtile  = blockIdx.x >> 1;
    const int h      = blockIdx.x & 1;

    const uint32_t sbase = smem_u32(smem);

    float acc[2][8][4];
#pragma unroll
    for (int i = 0; i < 2; ++i)
#pragma unroll
        for (int j = 0; j < 8; ++j)
#pragma unroll
            for (int k = 0; k < 4; ++k) acc[i][j][k] = 0.0f;

    ARegs rg;
    // prologue: B for stages 0,1 in flight; A stage 0 staged
    cpB(sbase + 0 * STAGE_BYTES + A_STAGE, h, 0, tid);
    cpB(sbase + 1 * STAGE_BYTES + A_STAGE, h, 1, tid);
    ldA(A, mtile, 0, tid, rg);
    stA(smem + 0 * STAGE_BYTES, tid, rg);
    cp_async_wait<1>();                 // B0 resident
    __syncthreads();

    for (int s = 0; s < 8; ++s) {
        const int buf  = s % NSTAGE;
        const int nbuf = (s + 1) % NSTAGE;
        const int pbuf = (s + 2) % NSTAGE;
        char* cbuf = smem + buf * STAGE_BYTES;

        if (s + 2 < 8)
            cpB(sbase + pbuf * STAGE_BYTES + A_STAGE, h, s + 2, tid);
        if (s + 1 < 8) {
            ldA(A, mtile, s + 1, tid, rg);
            stA(smem + nbuf * STAGE_BYTES, tid, rg);   // frees rg before MMAs
        }

#pragma unroll
        for (int k16l = 0; k16l < 2; ++k16l) {
            uint4 afr[2][2];
#pragma unroll
            for (int mtl = 0; mtl < 2; ++mtl) {
                int mtg = warp_m * 2 + mtl;
                char* blk = cbuf + (mtg * 2 + k16l) * 1024;
                afr[mtl][0] = *(uint4*)(blk + lane * 16);
                afr[mtl][1] = *(uint4*)(blk + 512 + lane * 16);
            }
#pragma unroll
            for (int ng = 0; ng < 2; ++ng) {       // keep only 4 B-frags live
                uint4 bfr[4];
#pragma unroll
                for (int j = 0; j < 4; ++j) {
                    int nt = warp_n * 8 + ng * 4 + j;
                    bfr[j] = *(uint4*)(cbuf + A_STAGE +
                                       ((nt * 2 + k16l) * 32 + lane) * 16);
                }
#pragma unroll
                for (int mtl = 0; mtl < 2; ++mtl)
#pragma unroll
                    for (int j = 0; j < 4; ++j) {
                        float* c = acc[mtl][ng * 4 + j];
                        mma_f16(c, (const uint32_t*)&afr[mtl][0], bfr[j].x, bfr[j].y);
                        mma_f16(c, (const uint32_t*)&afr[mtl][0], bfr[j].z, bfr[j].w);
                        mma_f16(c, (const uint32_t*)&afr[mtl][1], bfr[j].x, bfr[j].y);
                    }
            }
        }

        if (s + 2 < 8)      cp_async_wait<1>();    // B(s+1) resident
        else if (s + 1 < 8) cp_async_wait<0>();    // last prefetch drains
        __syncthreads();
    }

    // epilogue: c0=(g,2t) c1=(g,2t+1) c2=(g+8,2t) c3=(g+8,2t+1)
    const int g = lane >> 2, t = lane & 3;
#pragma unroll
    for (int mtl = 0; mtl < 2; ++mtl) {
        int row0 = mtile * 128 + warp_m * 32 + mtl * 16 + g;
#pragma unroll
        for (int ntl = 0; ntl < 8; ++ntl) {
            int col = h * 128 + warp_n * 64 + ntl * 8 + 2 * t;
            *(float2*)(out + (size_t)row0 * 256 + col) =
                make_float2(acc[mtl][ntl][0], acc[mtl][ntl][1]);
            *(float2*)(out + (size_t)(row0 + 8) * 256 + col) =
                make_float2(acc[mtl][ntl][2], acc[mtl][ntl][3]);
        }
    }
}

// ---------------------------------------------------------------------------
// Stage 2: in-place LIF scan. 256 CTAs x 64 threads (b x o-quarter).
// ---------------------------------------------------------------------------
constexpr int T_STEPS = 1024;
constexpr int OUT_C   = 256;
constexpr int TS      = 32;
constexpr int LPB     = 64;                 // lanes per block
constexpr int NTILES  = T_STEPS / TS;       // 32
constexpr int PIPE    = 2;

__global__ __launch_bounds__(LPB) void lif_scan_kernel(float* __restrict__ X)
{
    __shared__ float tile[PIPE][TS * LPB];   // 2 x 8KB

    const int tid = threadIdx.x;
    const int b   = blockIdx.x >> 2;         // batch
    const int qt  = blockIdx.x & 3;          // 64-lane quarter
    float* base  = X + (size_t)b * T_STEPS * OUT_C + qt * LPB;
    float* gbase = base + tid;

    uint32_t smem_base = smem_u32(&tile[0][0]);

    // per tile: 32 rows x 16 x 16B chunks = 512 chunks, 64 threads x 8
    auto issue_tile = [&](int c, int stage) {
#pragma unroll
        for (int k = 0; k < 8; ++k) {
            int chunk = tid + k * LPB;
            int row   = chunk >> 4;          // 0..31
            int c16   = chunk & 15;          // 0..15
            const void* g = (const char*)base +
                (size_t)(c * TS + row) * OUT_C * 4 + c16 * 16;
            uint32_t s = smem_base + stage * (TS * LPB * 4) + row * (LPB * 4) + c16 * 16;
            cp_async16(s, g);
        }
        cp_async_commit();
    };

    issue_tile(0, 0);
    issue_tile(1, 1);

    const float dcy_syn = 0.81873075307798185867f;   // exp(-0.2)
    const float dcy_mem = 0.90483741803595957316f;   // exp(-0.1)
    const float scl_mem = 1.0f - dcy_mem;

    float syn = 0.0f, mem = 0.0f;
    float carry = 0.0f;

    for (int c = 0; c < NTILES; ++c) {
        const int stage = c & (PIPE - 1);
        if (c == NTILES - 1) cp_async_wait<0>();
        else                 cp_async_wait<PIPE - 1>();
        __syncthreads();

        gbase[(size_t)(c * TS) * OUT_C] = carry;

        const float* sm = &tile[stage][tid];
#pragma unroll
        for (int i = 0; i < TS; ++i) {
            const int t = c * TS + i;
            if (t < T_STEPS - 1) {
                const float x    = sm[i * LPB];
                const float nsyn = fmaf(dcy_syn, syn, x);
                float nmem = fmaf(dcy_mem, mem, scl_mem * syn);
                if (mem > 1.0f) nmem = 0.0f;
                if (i < TS - 1)
                    gbase[(size_t)(t + 1) * OUT_C] = nmem;
                else
                    carry = nmem;
                syn = nsyn;
                mem = nmem;
            }
        }

        __syncthreads();
        if (c + PIPE < NTILES)
            issue_tile(c + PIPE, stage);
    }
}

// ---------------------------------------------------------------------------
extern "C" void kernel_launch(void* const* d_in, const int* in_sizes, int n_in,
                              void* d_out, int out_size)
{
    const float* inputs = (const float*)d_in[0];  // [64,1024,256]
    const float* w      = (const float*)d_in[1];  // [256,256]
    float* out          = (float*)d_out;          // [64,1024,256]

    cudaFuncSetAttribute(gemm_tc_kernel,
                         cudaFuncAttributeMaxDynamicSharedMemorySize, GEMM_SMEM);

    // Stage 0: W -> fp16 limb fragments
    prep_w_kernel<<<256, 256>>>(w);

    // Stage 1: x = inputs @ w -> d_out (3xFP16 mma.sync m16n8k16)
    gemm_tc_kernel<<<1024, 256, GEMM_SMEM>>>(inputs, out);

    // Stage 2: in-place scan x -> U  (256 CTAs = 64 batches x 4 quarters)
    lif_scan_kernel<<<64 * 4, LPB>>>(out);
}